// round 12
// baseline (speedup 1.0000x reference)
#include <cuda_runtime.h>

// Comparator4Bit: A,B are [N,4] float32 with exact {0,1} entries (MSB first).
// Outputs: a_gt_b [N], a_eq_b [N], concatenated into d_out (2N floats).
//
// FINAL — converged at the HBM ceiling (~6.3-6.5 TB/s achieved on a fixed
// 320 MiB 2:1 read:write stream). Best measured: 44.48us kernel / 53.25us
// dur_us, rel_err 0.0.
//
// Design decisions, each backed by a measured A/B:
//  - 512-thread blocks, one 4096-row tile per block (R6 vs R4: 48.7->44.5us).
//  - Warp-stride layout: consecutive lanes load consecutive 16B rows ->
//    every LDG.128 touches exactly 4 cache lines; every warp STG.32 fills
//    exactly one 128B line (R3/R4 vs R1/R2: row-per-thread layouts cost
//    16-32 lines per load wavefront).
//  - 16 independent front-batched __ldcs loads (evict-first, zero reuse).
//  - Default-policy scalar stores (__stcs measured harmful: R5, R7).
//  - No reg cap, no software pipelining (R9: 16-row batching under a cap
//    spills to local and costs 19us; R8: extra occupancy buys nothing —
//    the kernel is bandwidth-ceiling-bound, not latency-bound).
//  - Bit trick: entries are exactly 0.0f/1.0f, so pack each row to a 4-bit
//    int and compare; bit-identical to the reference boolean arithmetic.

#define ROWS_PER_THREAD 8
#define BLOCK_THREADS   512
#define TILE_ROWS       (BLOCK_THREADS * ROWS_PER_THREAD)   // 4096

__global__ __launch_bounds__(BLOCK_THREADS) void cmp4_kernel(
    const uint4* __restrict__ A,    // one uint4 per row
    const uint4* __restrict__ B,
    float* __restrict__ gt_out,     // N floats
    float* __restrict__ eq_out)     // N floats
{
    const int tile = blockIdx.x * TILE_ROWS;

    // Front-batch 16 independent, perfectly coalesced 128-bit streaming loads.
    uint4 a[ROWS_PER_THREAD], b[ROWS_PER_THREAD];
    #pragma unroll
    for (int k = 0; k < ROWS_PER_THREAD; k++) {
        int row = tile + k * BLOCK_THREADS + threadIdx.x;
        a[k] = __ldcs(&A[row]);
        b[k] = __ldcs(&B[row]);
    }

    #pragma unroll
    for (int k = 0; k < ROWS_PER_THREAD; k++) {
        int row = tile + k * BLOCK_THREADS + threadIdx.x;
        // Values are exactly 0.0f or 1.0f: nonzero pattern == logical 1.
        int av = ((a[k].x != 0u) << 3) | ((a[k].y != 0u) << 2) |
                 ((a[k].z != 0u) << 1) |  (a[k].w != 0u);
        int bv = ((b[k].x != 0u) << 3) | ((b[k].y != 0u) << 2) |
                 ((b[k].z != 0u) << 1) |  (b[k].w != 0u);
        gt_out[row] = (av > bv)  ? 1.0f : 0.0f;
        eq_out[row] = (av == bv) ? 1.0f : 0.0f;
    }
}

extern "C" void kernel_launch(void* const* d_in, const int* in_sizes, int n_in,
                              void* d_out, int out_size)
{
    const uint4* A = (const uint4*)d_in[0];
    const uint4* B = (const uint4*)d_in[1];
    int n_rows = in_sizes[0] / 4;          // N = 2^23

    float* out = (float*)d_out;
    float* gt_out = out;                   // first N floats
    float* eq_out = out + n_rows;          // next N floats

    int blocks = n_rows / TILE_ROWS;       // 2048 (N is a power of two)
    cmp4_kernel<<<blocks, BLOCK_THREADS>>>(A, B, gt_out, eq_out);
}